// round 4
// baseline (speedup 1.0000x reference)
#include <cuda_runtime.h>
#include <cstdint>
#include <cstddef>

// Problem constants
#define Bb 64
#define Tt 2048
#define Ii 128
#define Hh 256
#define Oo 128
#define Mm 256   // H - K1 + 1

// ---------------- scratch (device globals; no allocation allowed) ----------------
__device__ float g_uhats[Mm * Hh];
__device__ float g_vhats[Mm * Hh];
__device__ float g_bu[Mm];
__device__ float g_bv[Mm];
__device__ float g_U[Hh * Hh];
__device__ float g_V[Hh * Hh];
__device__ float g_W[Hh * Hh];
__device__ float g_xproj[(size_t)Bb * Tt * Hh];  // [B,T,H]
__device__ float g_hall [(size_t)Bb * Tt * Hh];  // [B,T,H]

// ---------------- helpers ----------------
__device__ __forceinline__ unsigned smem_u32(const void* p) {
    return (unsigned)__cvta_generic_to_shared(p);
}

// Packed f32x2 helpers (Blackwell 2xFP32 path; FFMA2 only via inline PTX)
__device__ __forceinline__ unsigned long long pack2(float lo, float hi) {
    unsigned long long r;
    asm("mov.b64 %0, {%1, %2};" : "=l"(r) : "f"(lo), "f"(hi));
    return r;
}
__device__ __forceinline__ void fma2(unsigned long long& d,
                                     unsigned long long a,
                                     unsigned long long b) {
    asm("fma.rn.f32x2 %0, %1, %2, %0;" : "+l"(d) : "l"(a), "l"(b));
}
__device__ __forceinline__ float2 unpack2(unsigned long long v) {
    float lo, hi;
    asm("mov.b64 {%0, %1}, %2;" : "=f"(lo), "=f"(hi) : "l"(v));
    return make_float2(lo, hi);
}

// mbarrier wait with cluster-scope acquire (observes peer DSMEM stores)
__device__ __forceinline__ void mbar_wait_cluster(unsigned addr, unsigned phase) {
    unsigned done;
    asm volatile(
        "{\n\t.reg .pred p;\n\t"
        "mbarrier.try_wait.parity.acquire.cluster.shared::cta.b64 p, [%1], %2;\n\t"
        "selp.b32 %0, 1, 0, p;\n\t}"
        : "=r"(done) : "r"(addr), "r"(phase) : "memory");
    while (!done) {
        asm volatile(
            "{\n\t.reg .pred p;\n\t"
            "mbarrier.try_wait.parity.acquire.cluster.shared::cta.b64 p, [%1], %2, 0x989680;\n\t"
            "selp.b32 %0, 1, 0, p;\n\t}"
            : "=r"(done) : "r"(addr), "r"(phase) : "memory");
    }
}

// ============================================================================
// Kernel 1: build u_hats / v_hats (mask + flips) and betas = 2/<u,u>
// ============================================================================
__global__ __launch_bounds__(256) void prep_kernel(const float* __restrict__ u_raw,
                                                   const float* __restrict__ v_raw) {
    __shared__ float red[256];
    int i = blockIdx.x & 255;
    bool isv = blockIdx.x >= 256;
    int j = threadIdx.x;
    float val = 0.f;
    if (!isv) {
        if (j >= 255 - i) val = u_raw[i * Hh + (255 - j)];
        g_uhats[i * Hh + j] = val;
    } else {
        if (j >= i) val = v_raw[(255 - i) * Hh + (255 - j)];
        g_vhats[i * Hh + j] = val;
    }
    red[j] = val * val;
    __syncthreads();
    for (int s = 128; s > 0; s >>= 1) {
        if (j < s) red[j] += red[j + s];
        __syncthreads();
    }
    if (j == 0) {
        float beta = 2.f / red[0];
        if (isv) g_bv[i] = beta; else g_bu[i] = beta;
    }
}

// ============================================================================
// Kernel 2: Householder chains, one warp per column of U/V.
// ============================================================================
__global__ __launch_bounds__(256) void chain_kernel() {
    int warp = (blockIdx.x * blockDim.x + threadIdx.x) >> 5;
    int lane = threadIdx.x & 31;
    int col = warp & 255;
    bool isv = warp >= 256;
    const float* hats  = isv ? g_vhats : g_uhats;
    const float* betas = isv ? g_bv    : g_bu;
    float* out         = isv ? g_V     : g_U;

    float c[8];
#pragma unroll
    for (int q = 0; q < 8; q++) c[q] = ((lane + 32 * q) == col) ? 1.f : 0.f;

    for (int i = 0; i < Mm; i++) {
        float u[8];
#pragma unroll
        for (int q = 0; q < 8; q++) u[q] = hats[i * Hh + lane + 32 * q];
        float s = 0.f;
#pragma unroll
        for (int q = 0; q < 8; q++) s = fmaf(u[q], c[q], s);
#pragma unroll
        for (int off = 16; off > 0; off >>= 1)
            s += __shfl_xor_sync(0xffffffffu, s, off);
        float sc = betas[i] * s;
#pragma unroll
        for (int q = 0; q < 8; q++) c[q] = fmaf(-sc, u[q], c[q]);
    }
#pragma unroll
    for (int q = 0; q < 8; q++) out[(size_t)(lane + 32 * q) * Hh + col] = c[q];
}

// ============================================================================
// Kernel 3: W = (U * diag(sigmas)) @ V.
// ============================================================================
__global__ __launch_bounds__(256) void wgemm_kernel(const float* __restrict__ sig) {
    __shared__ float su[Hh];
    int r = blockIdx.x;
    int cidx = threadIdx.x;
    su[cidx] = g_U[r * Hh + cidx] * sig[cidx];
    __syncthreads();
    float acc = 0.f;
#pragma unroll 8
    for (int k = 0; k < Hh; k++) acc = fmaf(su[k], g_V[(size_t)k * Hh + cidx], acc);
    g_W[r * Hh + cidx] = acc;
}

// ============================================================================
// Kernel 4/6: SGEMM  C[MxN] = A[MxK] * B[NxK]^T + bias[N]
// 128x128 tile, 8x8/thread, BK=16, 256 threads, packed-f32x2 inner product.
// ============================================================================
__global__ __launch_bounds__(256, 2) void sgemm_nt(const float* __restrict__ A,
                                                   const float* __restrict__ Bm,
                                                   const float* __restrict__ bias,
                                                   float* __restrict__ C,
                                                   int M, int N, int K) {
    __shared__ float As[16][128];
    __shared__ float Bs[16][128];
    int tid = threadIdx.x;
    int m0 = blockIdx.y * 128;
    int n0 = blockIdx.x * 128;
    int tx = tid & 15;   // n
    int ty = tid >> 4;   // m

    unsigned long long acc2[8][4];
#pragma unroll
    for (int i = 0; i < 8; i++)
#pragma unroll
        for (int j = 0; j < 4; j++) acc2[i][j] = 0ull;

    for (int k0 = 0; k0 < K; k0 += 16) {
#pragma unroll
        for (int i = 0; i < 2; i++) {
            int fid = tid + i * 256;
            int row = fid >> 2;
            int c4  = fid & 3;
            float4 va = *(const float4*)(A  + (size_t)(m0 + row) * K + k0 + c4 * 4);
            As[c4 * 4 + 0][row] = va.x; As[c4 * 4 + 1][row] = va.y;
            As[c4 * 4 + 2][row] = va.z; As[c4 * 4 + 3][row] = va.w;
            float4 vb = *(const float4*)(Bm + (size_t)(n0 + row) * K + k0 + c4 * 4);
            Bs[c4 * 4 + 0][row] = vb.x; Bs[c4 * 4 + 1][row] = vb.y;
            Bs[c4 * 4 + 2][row] = vb.z; Bs[c4 * 4 + 3][row] = vb.w;
        }
        __syncthreads();
#pragma unroll
        for (int kk = 0; kk < 16; kk++) {
            float4 a0 = *(const float4*)&As[kk][ty * 8];
            float4 a1 = *(const float4*)&As[kk][ty * 8 + 4];
            ulonglong2 b0 = *(const ulonglong2*)&Bs[kk][tx * 8];
            ulonglong2 b1 = *(const ulonglong2*)&Bs[kk][tx * 8 + 4];
            float av[8] = {a0.x, a0.y, a0.z, a0.w, a1.x, a1.y, a1.z, a1.w};
#pragma unroll
            for (int i = 0; i < 8; i++) {
                unsigned long long ad = pack2(av[i], av[i]);
                fma2(acc2[i][0], ad, b0.x);
                fma2(acc2[i][1], ad, b0.y);
                fma2(acc2[i][2], ad, b1.x);
                fma2(acc2[i][3], ad, b1.y);
            }
        }
        __syncthreads();
    }

    float bv[8];
#pragma unroll
    for (int j = 0; j < 8; j++) bv[j] = bias[n0 + tx * 8 + j];
#pragma unroll
    for (int i = 0; i < 8; i++) {
        size_t base = (size_t)(m0 + ty * 8 + i) * N + n0 + tx * 8;
        float2 p0 = unpack2(acc2[i][0]);
        float2 p1 = unpack2(acc2[i][1]);
        float2 p2 = unpack2(acc2[i][2]);
        float2 p3 = unpack2(acc2[i][3]);
        float4 o0, o1;
        o0.x = p0.x + bv[0]; o0.y = p0.y + bv[1];
        o0.z = p1.x + bv[2]; o0.w = p1.y + bv[3];
        o1.x = p2.x + bv[4]; o1.y = p2.y + bv[5];
        o1.z = p3.x + bv[6]; o1.w = p3.y + bv[7];
        *(float4*)(C + base)     = o0;
        *(float4*)(C + base + 4) = o1;
    }
}

// ============================================================================
// Kernel 5: recurrence. 2-CTA cluster per batch, 512 threads/CTA.
// Thread t: row r = t&127 (CTA-local), k-quarter q = t>>7 (64 k-values),
// W slice in 32 packed b64 regs. Partials reduced via smem; q==0 threads
// apply tanh and store. Peer h-half pushed via st.shared::cluster.v4 by 32
// threads, each doing a release-cluster mbarrier arrive (count=32); everyone
// waits with acquire-cluster try_wait. No barrier.cluster in the loop
// (avoids ~490cyc sync + per-step L1D flush).
// ============================================================================
__global__ __launch_bounds__(512, 1) __cluster_dims__(2, 1, 1)
void rnn_kernel() {
    __shared__ float hbuf[2][256];
    __shared__ float part[3][128];
    __shared__ __align__(8) unsigned long long mbar;

    unsigned rank;
    asm("mov.u32 %0, %%cluster_ctarank;" : "=r"(rank));
    int half = (int)rank;
    unsigned peer = rank ^ 1u;
    int b = blockIdx.x >> 1;
    int tid = threadIdx.x;
    int r = tid & 127;
    int q = tid >> 7;          // 0..3 -> k range [q*64, q*64+64)
    int grow = half * 128 + r;

    // W slice: W[grow][q*64 .. q*64+64) as 32 packed f32x2 regs
    unsigned long long w2[32];
    {
        const float4* wp = (const float4*)(g_W + (size_t)grow * Hh + q * 64);
#pragma unroll
        for (int j = 0; j < 16; j++) {
            float4 v = wp[j];
            w2[2 * j]     = pack2(v.x, v.y);
            w2[2 * j + 1] = pack2(v.z, v.w);
        }
    }

    if (tid < 256) hbuf[0][tid] = 0.f;
    unsigned mb = smem_u32((const void*)&mbar);
    if (tid == 0) {
        asm volatile("mbarrier.init.shared.b64 [%0], %1;" :: "r"(mb), "r"(32u) : "memory");
    }
    __syncthreads();
    // one-time cluster sync: mbarrier init + hbuf[0] visible before peer acts
    asm volatile("barrier.cluster.arrive.aligned;" ::: "memory");
    asm volatile("barrier.cluster.wait.aligned;" ::: "memory");

    const float* xp_ptr   = g_xproj + (size_t)b * Tt * Hh + grow;
    float*       hall_ptr = g_hall  + (size_t)b * Tt * Hh + grow;

    float xp0 = 0.f, xp1 = 0.f;
    if (q == 0) {
        xp0 = xp_ptr[0];
        xp1 = xp_ptr[Hh];
    }

    int cur = 0;
    unsigned phase = 0;
    for (int t = 0; t < Tt; t++) {
        float xp2 = 0.f;
        if (q == 0 && (t + 2) < Tt) xp2 = xp_ptr[(size_t)(t + 2) * Hh];

        // partial dot over this thread's 64 k-values (packed f32x2)
        const float* hp = hbuf[cur] + q * 64;
        unsigned long long a01 = 0ull, a23 = 0ull;
#pragma unroll
        for (int j = 0; j < 16; j++) {
            ulonglong2 hv = ((const ulonglong2*)hp)[j];
            fma2(a01, w2[2 * j],     hv.x);
            fma2(a23, w2[2 * j + 1], hv.y);
        }
        float2 p01 = unpack2(a01);
        float2 p23 = unpack2(a23);
        float s = (p01.x + p01.y) + (p23.x + p23.y);

        if (q) part[q - 1][r] = s;
        __syncthreads();

        int nxt = cur ^ 1;
        if (q == 0) {
            float v = tanhf(s + part[0][r] + part[1][r] + part[2][r] + xp0);
            hbuf[nxt][grow] = v;                  // own half, local
            hall_ptr[(size_t)t * Hh] = v;         // deferred output projection
            xp0 = xp1; xp1 = xp2;
        }
        __syncthreads();                          // local half of hbuf[nxt] ready

        if (t + 1 < Tt) {
            // push own half to peer (v4) + release-cluster arrive, 32 threads
            if (tid < 32) {
                int off = half * 128 + tid * 4;
                float4 v4 = *(const float4*)&hbuf[nxt][off];
                unsigned laddr = smem_u32(&hbuf[nxt][off]);
                asm volatile(
                    "{\n\t.reg .b32 ra, rb;\n\t"
                    "mapa.shared::cluster.u32 ra, %0, %5;\n\t"
                    "st.shared::cluster.v4.f32 [ra], {%1, %2, %3, %4};\n\t"
                    "mapa.shared::cluster.u32 rb, %6, %5;\n\t"
                    "mbarrier.arrive.release.cluster.shared::cluster.b64 _, [rb];\n\t}"
                    :: "r"(laddr), "f"(v4.x), "f"(v4.y), "f"(v4.z), "f"(v4.w),
                       "r"(peer), "r"(mb)
                    : "memory");
            }
            // wait for peer's half of hbuf[nxt]
            mbar_wait_cluster(mb, phase);
            phase ^= 1u;
        }
        cur = nxt;
    }

    // keep SMEM alive until the whole cluster is done with remote ops
    asm volatile("barrier.cluster.arrive.aligned;" ::: "memory");
    asm volatile("barrier.cluster.wait.aligned;" ::: "memory");
}

// ============================================================================
// launch
// ============================================================================
extern "C" void kernel_launch(void* const* d_in, const int* in_sizes, int n_in,
                              void* d_out, int out_size) {
    const float* x      = (const float*)d_in[0];
    const float* W_in   = (const float*)d_in[1];
    const float* b_in   = (const float*)d_in[2];
    const float* W_out  = (const float*)d_in[3];
    const float* b_out  = (const float*)d_in[4];
    const float* u_raw  = (const float*)d_in[5];
    const float* sigmas = (const float*)d_in[6];
    const float* v_raw  = (const float*)d_in[7];
    float* out = (float*)d_out;

    void* xp_v = nullptr;
    void* hall_v = nullptr;
    cudaGetSymbolAddress(&xp_v, g_xproj);
    cudaGetSymbolAddress(&hall_v, g_hall);
    float* xp = (float*)xp_v;
    float* hall = (float*)hall_v;

    prep_kernel<<<512, 256>>>(u_raw, v_raw);
    chain_kernel<<<64, 256>>>();
    wgemm_kernel<<<256, 256>>>(sigmas);
    sgemm_nt<<<dim3(Hh / 128, (Bb * Tt) / 128), 256>>>(x, W_in, b_in, xp,
                                                       Bb * Tt, Hh, Ii);
    rnn_kernel<<<Bb * 2, 512>>>();
    sgemm_nt<<<dim3(Oo / 128, (Bb * Tt) / 128), 256>>>(hall, W_out, b_out, out,
                                                       Bb * Tt, Oo, Hh);
}